// round 15
// baseline (speedup 1.0000x reference)
#include <cuda_runtime.h>

// x: [N=256, 3, 3, num=256, F=128] fp32, contiguous.
// out: [N, 3, 3, G=128, F=128] fp32.
// Winner per pair = larger rotation angle acos(clip((tr-1)/2,-1,1));
// acos decreasing => winner = smaller clamp(tr,-1,3); ties -> candidate 0.
//
// R15: two-pass, stream-count reduction (the single-kernel design is pinned
// at DRAM 82-84% by HBM turnaround across 27 address streams per warp).
//  Pass 1: diagonals -> mask (uchar4, 4MB, L2-resident scratch) + diag out.
//          10 streams/warp.
//  Pass 2: d-major over the 6 off-diagonal positions; per thread: mask read
//          (L2 hit), a[d],b[d] (512B apart, same DRAM page), one store.
//          3 streams/warp; chip-wide ~2 read slabs + 1 write slab.
// Extra traffic: +4MB mask (+1%); extra launch inside the same graph.

#define N_    256
#define G_    128
#define F4_   32                      // 128 floats = 32 float4
#define TOT1  (N_ * G_ * F4_)         // 1,048,576 pass-1 work items (2^20)
#define TOT2  (6 * TOT1)              // 6,291,456 pass-2 work items

// strides in float4 units
#define XSD   8192                    // per (d1*3+d2) step
#define XSM   32                      // per num step
#define XSN   73728                   // 9*8192
#define OSD   4096
#define OSG   32
#define OSN   36864                   // 9*4096

// 4 MB select-mask scratch: one uchar4 per (n,g,f4), linear index == pass-1 idx.
__device__ uchar4 g_mask[TOT1];

__device__ __forceinline__ float clamp_tr(float t) {
    return fminf(fmaxf(t, -1.0f), 3.0f);
}

__device__ __forceinline__ float4 sel4(bool sx, bool sy, bool sz, bool sw,
                                       const float4& a, const float4& b) {
    float4 r;
    r.x = sx ? b.x : a.x;
    r.y = sy ? b.y : a.y;
    r.z = sz ? b.z : a.z;
    r.w = sw ? b.w : a.w;
    return r;
}

// ---- pass 1: diagonals -> mask + diagonal outputs ----
__global__ __launch_bounds__(256, 6)
void pool_pass1(const float4* __restrict__ xv, float4* __restrict__ ov) {
    int idx = blockIdx.x * blockDim.x + threadIdx.x;

    int f4 = idx & (F4_ - 1);
    int g  = (idx >> 5) & (G_ - 1);
    int n  = idx >> 12;

    const float4* pa = xv + n * XSN + (2 * g) * XSM + f4;
    const float4* pb = pa + XSM;
    float4*       po = ov + n * OSN + g * OSG + f4;

    float4 a0 = __ldcs(pa + 0 * XSD);
    float4 a4 = __ldcs(pa + 4 * XSD);
    float4 a8 = __ldcs(pa + 8 * XSD);
    float4 b0 = __ldcs(pb + 0 * XSD);
    float4 b4 = __ldcs(pb + 4 * XSD);
    float4 b8 = __ldcs(pb + 8 * XSD);

    // candidate 1 wins only on strictly smaller clamped trace
    bool sx = clamp_tr(b0.x + b4.x + b8.x) < clamp_tr(a0.x + a4.x + a8.x);
    bool sy = clamp_tr(b0.y + b4.y + b8.y) < clamp_tr(a0.y + a4.y + a8.y);
    bool sz = clamp_tr(b0.z + b4.z + b8.z) < clamp_tr(a0.z + a4.z + a8.z);
    bool sw = clamp_tr(b0.w + b4.w + b8.w) < clamp_tr(a0.w + a4.w + a8.w);

    // default (evict-normal) store: keep the mask resident in L2 for pass 2
    g_mask[idx] = make_uchar4(sx, sy, sz, sw);

    __stcs(po + 0 * OSD, sel4(sx, sy, sz, sw, a0, b0));
    __stcs(po + 4 * OSD, sel4(sx, sy, sz, sw, a4, b4));
    __stcs(po + 8 * OSD, sel4(sx, sy, sz, sw, a8, b8));
}

// ---- pass 2: off-diagonals, d-major (all co-resident CTAs in one d-slab) ----
__global__ __launch_bounds__(256, 8)
void pool_pass2(const float4* __restrict__ xv, float4* __restrict__ ov) {
    int idx = blockIdx.x * blockDim.x + threadIdx.x;

    int mi   = idx & (TOT1 - 1);      // (n,g,f4) linear index
    int dIdx = idx >> 20;             // 0..5
    int d    = dIdx + 1 + (dIdx > 2); // -> 1,2,3,5,6,7

    int f4 = mi & (F4_ - 1);
    int g  = (mi >> 5) & (G_ - 1);
    int n  = mi >> 12;

    uchar4 m = g_mask[mi];            // L2 hit (written in pass 1)

    const float4* pa = xv + n * XSN + (2 * g) * XSM + d * XSD + f4;
    float4 a = __ldcs(pa);
    float4 b = __ldcs(pa + XSM);

    __stcs(ov + n * OSN + g * OSG + d * OSD + f4,
           sel4(m.x, m.y, m.z, m.w, a, b));
}

extern "C" void kernel_launch(void* const* d_in, const int* in_sizes, int n_in,
                              void* d_out, int out_size) {
    const float4* x = (const float4*)d_in[0];
    float4* out = (float4*)d_out;
    (void)in_sizes; (void)n_in; (void)out_size;
    pool_pass1<<<TOT1 / 256, 256>>>(x, out);
    pool_pass2<<<TOT2 / 256, 256>>>(x, out);
}

// round 16
// speedup vs baseline: 1.0031x; 1.0031x over previous
#include <cuda_runtime.h>

// x: [N=256, 3, 3, num=256, F=128] fp32, contiguous.
// out: [N, 3, 3, G=128, F=128] fp32.
// Winner per pair = larger rotation angle acos(clip((tr-1)/2,-1,1));
// acos decreasing => winner = smaller clamp(tr,-1,3); ties -> candidate 0.
//
// R15: two-pass, stream-count reduction (the single-kernel design is pinned
// at DRAM 82-84% by HBM turnaround across 27 address streams per warp).
//  Pass 1: diagonals -> mask (uchar4, 4MB, L2-resident scratch) + diag out.
//          10 streams/warp.
//  Pass 2: d-major over the 6 off-diagonal positions; per thread: mask read
//          (L2 hit), a[d],b[d] (512B apart, same DRAM page), one store.
//          3 streams/warp; chip-wide ~2 read slabs + 1 write slab.
// Extra traffic: +4MB mask (+1%); extra launch inside the same graph.

#define N_    256
#define G_    128
#define F4_   32                      // 128 floats = 32 float4
#define TOT1  (N_ * G_ * F4_)         // 1,048,576 pass-1 work items (2^20)
#define TOT2  (6 * TOT1)              // 6,291,456 pass-2 work items

// strides in float4 units
#define XSD   8192                    // per (d1*3+d2) step
#define XSM   32                      // per num step
#define XSN   73728                   // 9*8192
#define OSD   4096
#define OSG   32
#define OSN   36864                   // 9*4096

// 4 MB select-mask scratch: one uchar4 per (n,g,f4), linear index == pass-1 idx.
__device__ uchar4 g_mask[TOT1];

__device__ __forceinline__ float clamp_tr(float t) {
    return fminf(fmaxf(t, -1.0f), 3.0f);
}

__device__ __forceinline__ float4 sel4(bool sx, bool sy, bool sz, bool sw,
                                       const float4& a, const float4& b) {
    float4 r;
    r.x = sx ? b.x : a.x;
    r.y = sy ? b.y : a.y;
    r.z = sz ? b.z : a.z;
    r.w = sw ? b.w : a.w;
    return r;
}

// ---- pass 1: diagonals -> mask + diagonal outputs ----
__global__ __launch_bounds__(256, 6)
void pool_pass1(const float4* __restrict__ xv, float4* __restrict__ ov) {
    int idx = blockIdx.x * blockDim.x + threadIdx.x;

    int f4 = idx & (F4_ - 1);
    int g  = (idx >> 5) & (G_ - 1);
    int n  = idx >> 12;

    const float4* pa = xv + n * XSN + (2 * g) * XSM + f4;
    const float4* pb = pa + XSM;
    float4*       po = ov + n * OSN + g * OSG + f4;

    float4 a0 = __ldcs(pa + 0 * XSD);
    float4 a4 = __ldcs(pa + 4 * XSD);
    float4 a8 = __ldcs(pa + 8 * XSD);
    float4 b0 = __ldcs(pb + 0 * XSD);
    float4 b4 = __ldcs(pb + 4 * XSD);
    float4 b8 = __ldcs(pb + 8 * XSD);

    // candidate 1 wins only on strictly smaller clamped trace
    bool sx = clamp_tr(b0.x + b4.x + b8.x) < clamp_tr(a0.x + a4.x + a8.x);
    bool sy = clamp_tr(b0.y + b4.y + b8.y) < clamp_tr(a0.y + a4.y + a8.y);
    bool sz = clamp_tr(b0.z + b4.z + b8.z) < clamp_tr(a0.z + a4.z + a8.z);
    bool sw = clamp_tr(b0.w + b4.w + b8.w) < clamp_tr(a0.w + a4.w + a8.w);

    // default (evict-normal) store: keep the mask resident in L2 for pass 2
    g_mask[idx] = make_uchar4(sx, sy, sz, sw);

    __stcs(po + 0 * OSD, sel4(sx, sy, sz, sw, a0, b0));
    __stcs(po + 4 * OSD, sel4(sx, sy, sz, sw, a4, b4));
    __stcs(po + 8 * OSD, sel4(sx, sy, sz, sw, a8, b8));
}

// ---- pass 2: off-diagonals, d-major (all co-resident CTAs in one d-slab) ----
__global__ __launch_bounds__(256, 8)
void pool_pass2(const float4* __restrict__ xv, float4* __restrict__ ov) {
    int idx = blockIdx.x * blockDim.x + threadIdx.x;

    int mi   = idx & (TOT1 - 1);      // (n,g,f4) linear index
    int dIdx = idx >> 20;             // 0..5
    int d    = dIdx + 1 + (dIdx > 2); // -> 1,2,3,5,6,7

    int f4 = mi & (F4_ - 1);
    int g  = (mi >> 5) & (G_ - 1);
    int n  = mi >> 12;

    uchar4 m = g_mask[mi];            // L2 hit (written in pass 1)

    const float4* pa = xv + n * XSN + (2 * g) * XSM + d * XSD + f4;
    float4 a = __ldcs(pa);
    float4 b = __ldcs(pa + XSM);

    __stcs(ov + n * OSN + g * OSG + d * OSD + f4,
           sel4(m.x, m.y, m.z, m.w, a, b));
}

extern "C" void kernel_launch(void* const* d_in, const int* in_sizes, int n_in,
                              void* d_out, int out_size) {
    const float4* x = (const float4*)d_in[0];
    float4* out = (float4*)d_out;
    (void)in_sizes; (void)n_in; (void)out_size;
    pool_pass1<<<TOT1 / 256, 256>>>(x, out);
    pool_pass2<<<TOT2 / 256, 256>>>(x, out);
}

// round 17
// speedup vs baseline: 1.0395x; 1.0363x over previous
#include <cuda_runtime.h>

// x: [N=256, 3, 3, num=256, F=128] fp32, contiguous.
// out: [N, 3, 3, G=128, F=128] fp32.
// Winner per pair = larger rotation angle acos(clip((tr-1)/2,-1,1));
// acos decreasing => winner = smaller clamp(tr,-1,3); ties -> candidate 0.
//
// FINAL — locked R6 configuration (best wall 69.63us, reproduced 69.66us).
// Nine variants measured: occupancy 32<->48 warps, CTA 128/256/512,
// persistent grid, 128/256-bit accesses, write-back stores, and a two-pass
// L2-mask design with 3 streams/warp (falsified the stream-count theory:
// DRAM dropped to 76%). All neutral or regressions. Traffic is provably at
// the 453 MB floor (per-element winner touches every sector of both
// candidates); wall is within ~2.5% of the achieved mixed 2:1 read:write
// HBM3e ceiling (~6.6 TB/s, DRAM busy 83-84%). Not SASS-addressable.
//
// Structure: one thread per (n,g,f4) float4 chunk. Diagonals first (6
// streaming loads) -> select mask from clamped traces -> retire d=0,4,8,
// then one deep 12-load batch for the off-diagonals (deep MLP per warp is
// what holds DRAM at the plateau — shallow-batch variants lose). __ldcs /
// __stcs keep the zero-reuse streams from churning L2.

#define N_    256
#define G_    128
#define F4_   32                      // 128 floats = 32 float4
#define TOT   (N_ * G_ * F4_)         // 1,048,576 threads

// strides in float4 units
#define XSD   8192                    // per (d1*3+d2) step
#define XSM   32                      // per num step
#define XSN   73728                   // 9*8192
#define OSD   4096
#define OSG   32
#define OSN   36864                   // 9*4096

__device__ __forceinline__ float clamp_tr(float t) {
    return fminf(fmaxf(t, -1.0f), 3.0f);
}

__device__ __forceinline__ float4 sel4(bool sx, bool sy, bool sz, bool sw,
                                       const float4& a, const float4& b) {
    float4 r;
    r.x = sx ? b.x : a.x;
    r.y = sy ? b.y : a.y;
    r.z = sz ? b.z : a.z;
    r.w = sw ? b.w : a.w;
    return r;
}

__global__ __launch_bounds__(256, 4)
void Pooling_5866925326754_kernel(const float4* __restrict__ xv,
                                  float4* __restrict__ ov) {
    int idx = blockIdx.x * blockDim.x + threadIdx.x;
    if (idx >= TOT) return;

    int f4 = idx & (F4_ - 1);
    int g  = (idx >> 5) & (G_ - 1);
    int n  = idx >> 12;

    const float4* pa = xv + n * XSN + (2 * g) * XSM + f4;
    const float4* pb = pa + XSM;
    float4*       po = ov + n * OSN + g * OSG + f4;

    // ---- diagonal loads (6), streaming policy ----
    float4 a0 = __ldcs(pa + 0 * XSD);
    float4 a4 = __ldcs(pa + 4 * XSD);
    float4 a8 = __ldcs(pa + 8 * XSD);
    float4 b0 = __ldcs(pb + 0 * XSD);
    float4 b4 = __ldcs(pb + 4 * XSD);
    float4 b8 = __ldcs(pb + 8 * XSD);

    // candidate 1 wins only on strictly smaller clamped trace
    bool sx = clamp_tr(b0.x + b4.x + b8.x) < clamp_tr(a0.x + a4.x + a8.x);
    bool sy = clamp_tr(b0.y + b4.y + b8.y) < clamp_tr(a0.y + a4.y + a8.y);
    bool sz = clamp_tr(b0.z + b4.z + b8.z) < clamp_tr(a0.z + a4.z + a8.z);
    bool sw = clamp_tr(b0.w + b4.w + b8.w) < clamp_tr(a0.w + a4.w + a8.w);

    // retire the diagonal positions immediately (frees 6 float4 of liveness)
    __stcs(po + 0 * OSD, sel4(sx, sy, sz, sw, a0, b0));
    __stcs(po + 4 * OSD, sel4(sx, sy, sz, sw, a4, b4));
    __stcs(po + 8 * OSD, sel4(sx, sy, sz, sw, a8, b8));

    // ---- off-diagonal positions: 1,2,3,5,6,7 (12-deep load batch) ----
    float4 a1 = __ldcs(pa + 1 * XSD);
    float4 a2 = __ldcs(pa + 2 * XSD);
    float4 a3 = __ldcs(pa + 3 * XSD);
    float4 a5 = __ldcs(pa + 5 * XSD);
    float4 a6 = __ldcs(pa + 6 * XSD);
    float4 a7 = __ldcs(pa + 7 * XSD);
    float4 b1 = __ldcs(pb + 1 * XSD);
    float4 b2 = __ldcs(pb + 2 * XSD);
    float4 b3 = __ldcs(pb + 3 * XSD);
    float4 b5 = __ldcs(pb + 5 * XSD);
    float4 b6 = __ldcs(pb + 6 * XSD);
    float4 b7 = __ldcs(pb + 7 * XSD);

    __stcs(po + 1 * OSD, sel4(sx, sy, sz, sw, a1, b1));
    __stcs(po + 2 * OSD, sel4(sx, sy, sz, sw, a2, b2));
    __stcs(po + 3 * OSD, sel4(sx, sy, sz, sw, a3, b3));
    __stcs(po + 5 * OSD, sel4(sx, sy, sz, sw, a5, b5));
    __stcs(po + 6 * OSD, sel4(sx, sy, sz, sw, a6, b6));
    __stcs(po + 7 * OSD, sel4(sx, sy, sz, sw, a7, b7));
}

extern "C" void kernel_launch(void* const* d_in, const int* in_sizes, int n_in,
                              void* d_out, int out_size) {
    const float4* x = (const float4*)d_in[0];
    float4* out = (float4*)d_out;
    (void)in_sizes; (void)n_in; (void)out_size;
    Pooling_5866925326754_kernel<<<TOT / 256, 256>>>(x, out);
}